// round 11
// baseline (speedup 1.0000x reference)
#include <cuda_runtime.h>
#include <cuda_bf16.h>

// Problem shapes (fixed by the dataset)
#define B_   128
#define P_   4096
#define L_   128
#define TPB  128
#define PPT  2
#define BLOCKS_PER_B (P_ / (TPB * PPT)) // 16
#define NB   (B_ * BLOCKS_PER_B)        // 2048 partials
#define NBK  64                         // x-buckets for proposal sort

// ---- fixed scratch (device globals; no allocations allowed) ----
__device__ float4 g_box1[B_][L_];   // labels sorted by lx  : (lx, ly, lx+lw, ly+lh)
__device__ float2 g_lt1 [B_][L_];   // (la, tag-as-float-bits)
__device__ float  g_key1[B_][L_];   // lx (ascending)
__device__ float4 g_box2[B_][L_];   // labels sorted by lx+lw
__device__ float2 g_lt2 [B_][L_];
__device__ float  g_key2[B_][L_];   // lx+lw (ascending)
__device__ int    g_order[B_][P_];  // proposal permutation (x-sorted, stable)
__device__ float  g_partials[NB];
__device__ unsigned int g_count = 0;

__device__ __forceinline__ float huber1(float e) {
    float a = fabsf(e);
    return (a <= 1.0f) ? 0.5f * e * e : a - 0.5f;
}
__device__ __forceinline__ float frcp(float x) {
    float r;
    asm("rcp.approx.f32 %0, %1;" : "=f"(r) : "f"(x));
    return r;
}
__device__ __forceinline__ float fsub_fma(float a, float b) {  // a-b, fma pipe imm form
    float d;
    asm("fma.rn.f32 %0, %1, 0fBF800000, %2;" : "=f"(d) : "f"(b), "f"(a));
    return d;
}

// ---- kernel 1: sort 128 labels per batch by lx and by lx+lw (rank sort) ----
__global__ __launch_bounds__(L_)
void label_sort_kernel(const float* __restrict__ labels)
{
    __shared__ float k1s[L_], k2s[L_];
    const int b = blockIdx.x, t = threadIdx.x;
    float4 v = ((const float4*)(labels + (size_t)b * L_ * 4))[t];
    float lx = v.x, ly = v.y, lw = v.z, lh = v.w;
    float lz = lx + lw;
    k1s[t] = lx; k2s[t] = lz;
    __syncthreads();
    int r1 = 0, r2 = 0;
#pragma unroll 8
    for (int j = 0; j < L_; ++j) {
        float a = k1s[j]; r1 += (a < lx) || (a == lx && j < t);
        float c = k2s[j]; r2 += (c < lz) || (c == lz && j < t);
    }
    float4 box = make_float4(lx, ly, lz, ly + lh);
    float2 lt  = make_float2(lw * lh, __int_as_float(127 - t)); // tag = 127 - orig idx
    g_box1[b][r1] = box; g_lt1[b][r1] = lt; g_key1[b][r1] = lx;
    g_box2[b][r2] = box; g_lt2[b][r2] = lt; g_key2[b][r2] = lz;
}

// ---- kernel 2: deterministic stable counting sort of 4096 proposals by x ----
__global__ __launch_bounds__(128)
void prop_sort_kernel(const float* __restrict__ roi)
{
    __shared__ int s_cnt[NBK][128];   // 32 KB
    __shared__ int s_base[NBK];
    const int b = blockIdx.x, t = threadIdx.x;
    for (int i = t; i < NBK * 128; i += 128) ((int*)s_cnt)[i] = 0;
    __syncthreads();
    const float* rb = roi + (size_t)b * P_ * 4;
    // phase 1: per-thread histograms over its 32 consecutive proposals
    for (int k = 0; k < 32; ++k) {
        int src = t * 32 + k;
        float x = rb[src * 4];                       // raw x in [0,40)
        int bk = min(NBK - 1, max(0, (int)(x * 1.6f)));
        s_cnt[bk][t]++;                              // only thread t touches column t
    }
    __syncthreads();
    // phase 2: exclusive scan (thread-within-bucket, then bucket bases)
    if (t < NBK) {
        int run = 0;
        for (int j = 0; j < 128; ++j) { int c = s_cnt[t][j]; s_cnt[t][j] = run; run += c; }
        s_base[t] = run;
    }
    __syncthreads();
    if (t == 0) {
        int run = 0;
        for (int bk = 0; bk < NBK; ++bk) { int c = s_base[bk]; s_base[bk] = run; run += c; }
    }
    __syncthreads();
    // phase 3: stable scatter (thread t processes its 32 in order)
    for (int k = 0; k < 32; ++k) {
        int src = t * 32 + k;
        float x = rb[src * 4];
        int bk = min(NBK - 1, max(0, (int)(x * 1.6f)));
        int dst = s_base[bk] + s_cnt[bk][t]++;
        g_order[b][dst] = src;
    }
}

// ---- kernel 3: main loss kernel with per-warp label-candidate pruning ----
__global__ __launch_bounds__(TPB)
void classifier_loss_kernel(const float* __restrict__ cls,
                            const float* __restrict__ deltas,
                            const float* __restrict__ roi,
                            const float* __restrict__ labels,
                            const int*   __restrict__ neg_flag,
                            float*       __restrict__ out)
{
    __shared__ float4 sb1[L_], sb2[L_];
    __shared__ float2 st1[L_], st2[L_];
    __shared__ float  sk1[L_], sk2[L_];
    __shared__ float  s_red[TPB];
    __shared__ bool   s_last;
    __shared__ double s_d[TPB];

    const int tid  = threadIdx.x;
    const int b    = blockIdx.y;
    const int warp = tid >> 5, lane = tid & 31;

    if (tid < L_) {
        sb1[tid] = g_box1[b][tid]; st1[tid] = g_lt1[b][tid]; sk1[tid] = g_key1[b][tid];
        sb2[tid] = g_box2[b][tid]; st2[tid] = g_lt2[b][tid]; sk2[tid] = g_key2[b][tid];
    }
    __syncthreads();

    // Warp handles 64 CONSECUTIVE sorted positions (tight x-window):
    //   position = blk*256 + warp*64 + q*32 + lane
    int   sp[PPT];
    float rx[PPT], ry[PPT], rx2[PPT], ry2[PPT], rA[PPT];
    int   best[PPT];
    float rxmin_t = 1e30f, rx2max_t = -1e30f;
#pragma unroll
    for (int q = 0; q < PPT; ++q) {
        int pos = blockIdx.x * (TPB * PPT) + warp * 64 + q * 32 + lane;
        int s   = g_order[b][pos];
        sp[q]   = s;
        float4 r = ((const float4*)(roi + (size_t)b * P_ * 4))[s];
        float x = r.x * 32.0f, y = r.y * 32.0f, w = r.z * 32.0f, h = r.w * 32.0f;
        rx[q] = x; ry[q] = y; rx2[q] = x + w; ry2[q] = y + h;
        rA[q] = w * h;
        best[q] = (int)0x80000000;
        rxmin_t  = fminf(rxmin_t, x);
        rx2max_t = fmaxf(rx2max_t, x + w);
    }
    // warp-wide min/max (all 32 lanes active)
#pragma unroll
    for (int off = 16; off > 0; off >>= 1) {
        rxmin_t  = fminf(rxmin_t,  __shfl_xor_sync(0xFFFFFFFFu, rxmin_t,  off));
        rx2max_t = fmaxf(rx2max_t, __shfl_xor_sync(0xFFFFFFFFu, rx2max_t, off));
    }

    // Candidate window (warp-uniform). Labels outside either list's range have
    // dx<0 for EVERY lane in the warp -> score <= 0 -> cannot affect argmax/pos.
    int lo = 0, hi = L_;
    while (lo < hi) { int mid = (lo + hi) >> 1; if (sk1[mid] <= rx2max_t) lo = mid + 1; else hi = mid; }
    const int A = lo;                       // list1 prefix [0, A):  lx <= rx2max
    lo = 0; hi = L_;
    while (lo < hi) { int mid = (lo + hi) >> 1; if (sk2[mid] < rxmin_t) lo = mid + 1; else hi = mid; }
    const int Bq = lo;                      // list2 suffix [Bq,128): lx+lw >= rxmin
    const int n1 = A, n2 = L_ - Bq;
    const float4* Lb; const float2* Lt; int i0, n;
    if (n1 <= n2) { Lb = sb1; Lt = st1; i0 = 0;  n = n1; }
    else          { Lb = sb2; Lt = st2; i0 = Bq; n = n2; }

    // argmax_l of iou == argmax_l of inter/(la + rA)  (monotone transform).
    // Single-clamp: sc = dx * max(dy,0) / (la+rA) -> sign-rejects non-overlaps.
    // Signed packed argmax: high 25 bits = score bits, low 7 = 127-orig_idx
    // (first-max tie-break identical to jnp.argmax). pos <=> (best & ~0x7F) > 0.
#pragma unroll 4
    for (int i = i0; i < i0 + n; ++i) {
        float4 lb = Lb[i];
        float2 lt = Lt[i];
        int tag = __float_as_int(lt.y);
#pragma unroll
        for (int q = 0; q < PPT; ++q) {
            float rc = frcp(lt.x + rA[q]);
            float dx = fsub_fma(fminf(lb.z, rx2[q]), fmaxf(lb.x, rx[q]));
            float dy = fsub_fma(fminf(lb.w, ry2[q]), fmaxf(lb.y, ry[q]));
            float sy = fmaxf(dy, 0.0f);
            float sc = (dx * sy) * rc;
            int pk = (int)((__float_as_uint(sc) & 0xFFFFFF80u) | (unsigned)tag);
            best[q] = max(best[q], pk);
        }
    }

    const int neg = __ldg(neg_flag);
    const float LOG01 = -2.3025850929940457f;   // log(0.1)
    const float LOG09 = -0.10536051565782628f;  // log(0.9)
    const float* cb = cls    + (size_t)b * 2 * P_;
    const float* db = deltas + (size_t)b * 4 * P_;
    const float* lab = labels + (size_t)b * L_ * 4;

    float per_sum = 0.0f;
#pragma unroll
    for (int q = 0; q < PPT; ++q) {
        const int s  = sp[q];
        const int be = best[q];
        int  bidx = 127 - (be & 0x7F);
        bool pos  = ((be & (int)0xFFFFFF80) > 0) && (bidx > 0);

        float l0 = cb[s];
        float l1 = cb[P_ + s];
        float mx = fmaxf(l0, l1);
        float e0 = __expf(l0 - mx);
        float e1 = __expf(l1 - mx);
        float inv = frcp(e0 + e1);
        float pr0 = e0 * inv, pr1 = e1 * inv;

        float per;
        if (pos) {
            float ce_pos = -(pr0 * LOG01 + pr1 * LOG09);
            float4 mv = ((const float4*)lab)[bidx];   // (lx, ly, lw, lh) orig order
            float rw = rx2[q] - rx[q];
            float rh = ry2[q] - ry[q];
            float invw = frcp(rw);
            float invh = frcp(rh);
            float tx = (mv.x - rx[q]) * invw;
            float ty = (mv.y - ry[q]) * invh;
            float tw = __logf(fmaxf(mv.z * invw, 1e-8f));
            float th = __logf(fmaxf(mv.w * invh, 1e-8f));
            float hx = huber1(tx - db[s]);
            float hy = huber1(ty - db[P_ + s]);
            float hw = huber1(tw - db[2 * P_ + s]);
            float hh = huber1(th - db[3 * P_ + s]);
            per = 0.5f * (hx + hy + hw + hh) + ce_pos;   // 2 * mean(huber)
        } else {
            float ce_neg = -(pr0 * LOG09 + pr1 * LOG01);
            per = (neg > 0) ? ce_neg : 0.0f;
        }
        per_sum += per;
    }

    // Deterministic block reduction (proposal->block mapping is deterministic:
    // the counting sort is stable and data-dependent only).
    s_red[tid] = per_sum;
    __syncthreads();
#pragma unroll
    for (int st = TPB / 2; st > 0; st >>= 1) {
        if (tid < st) s_red[tid] += s_red[tid + st];
        __syncthreads();
    }
    if (tid == 0) {
        g_partials[b * BLOCKS_PER_B + blockIdx.x] = s_red[0];
        __threadfence();
        unsigned t = atomicAdd(&g_count, 1u);
        s_last = (t == NB - 1);
    }
    __syncthreads();

    if (s_last) {
        double acc = 0.0;
#pragma unroll
        for (int i = tid; i < NB; i += TPB)
            acc += (double)__ldcg(&g_partials[i]);
        s_d[tid] = acc;
        __syncthreads();
#pragma unroll
        for (int st = TPB / 2; st > 0; st >>= 1) {
            if (tid < st) s_d[tid] += s_d[tid + st];
            __syncthreads();
        }
        if (tid == 0) {
            out[0]  = (float)s_d[0];
            g_count = 0;   // reset for next graph replay
        }
    }
}

extern "C" void kernel_launch(void* const* d_in, const int* in_sizes, int n_in,
                              void* d_out, int out_size)
{
    const float* cls    = (const float*)d_in[0];  // [B, 2P]
    const float* deltas = (const float*)d_in[1];  // [B, 4P]
    const float* roi    = (const float*)d_in[2];  // [B, P, 4]
    const float* labels = (const float*)d_in[3];  // [B, L, 4]
    const int*   negf   = (const int*)  d_in[4];  // scalar

    label_sort_kernel<<<B_, L_>>>(labels);
    prop_sort_kernel<<<B_, 128>>>(roi);
    dim3 grid(BLOCKS_PER_B, B_);
    classifier_loss_kernel<<<grid, TPB>>>(cls, deltas, roi, labels, negf,
                                          (float*)d_out);
    (void)in_sizes; (void)n_in; (void)out_size;
}

// round 14
// speedup vs baseline: 1.2436x; 1.2436x over previous
#include <cuda_runtime.h>
#include <cuda_bf16.h>

// Problem shapes (fixed by the dataset)
#define B_   128
#define P_   4096
#define L_   128
#define TPB  128
#define PPT  4                          // proposals per thread
#define BLOCKS_PER_B (P_ / (TPB * PPT)) // 8
#define NB   (B_ * BLOCKS_PER_B)        // 1024 partials

__device__ float        g_partials[NB];
__device__ unsigned int g_count = 0;

__device__ __forceinline__ float huber1(float e) {
    float a = fabsf(e);
    return (a <= 1.0f) ? 0.5f * e * e : a - 0.5f;
}

__global__ __launch_bounds__(TPB, 8)
void classifier_loss_kernel(const float* __restrict__ cls,
                            const float* __restrict__ deltas,
                            const float* __restrict__ roi,
                            const float* __restrict__ labels,
                            const int*   __restrict__ neg_flag,
                            float*       __restrict__ out)
{
    __shared__ float4 s_box[L_];   // lx, ly, lx+lw, ly+lh
    __shared__ float  s_la[L_];    // lw*lh
    __shared__ float2 s_wh[L_];    // lw, lh (exact, for targets)
    __shared__ float  s_red[TPB];
    __shared__ bool   s_last;
    __shared__ double s_d[TPB];

    const int tid = threadIdx.x;
    const int b   = blockIdx.y;
    const int pb  = blockIdx.x * (TPB * PPT) + tid;   // proposal base

    if (tid < L_) {
        float4 v = ((const float4*)(labels + (size_t)b * L_ * 4))[tid];
        s_box[tid] = make_float4(v.x, v.y, v.x + v.z, v.y + v.w);
        s_la[tid]  = v.z * v.w;
        s_wh[tid]  = make_float2(v.z, v.w);
    }
    __syncthreads();

    // Per-proposal state (SCALE=32 is an exact pow2 multiply)
    float rx[PPT], ry[PPT], rx2[PPT], ry2[PPT], rA[PPT];
    int best[PPT];
#pragma unroll
    for (int q = 0; q < PPT; ++q) {
        float4 r = ((const float4*)(roi + (size_t)b * P_ * 4))[pb + q * TPB];
        float x = r.x * 32.0f, y = r.y * 32.0f, w = r.z * 32.0f, h = r.w * 32.0f;
        rx[q] = x; ry[q] = y; rx2[q] = x + w; ry2[q] = y + h;
        rA[q] = w * h;
        best[q] = (int)0x80000000;   // INT_MIN: loses to every packed score
    }

    // argmax_l of iou == argmax_l of inter/(la + rA)  (monotone transform;
    // union = la + rA - inter, and x -> x/(1+x) is monotone).
    // Single-clamp trick: sc = dx * max(dy,0) / (la+rA):
    //   dy<0 -> sc = +/-0 ; dx<0,dy>=0 -> sc<0 ; overlap -> sc>0 correct.
    // Signed packed argmax: high 25 bits = score bits, low 7 bits = 127-l;
    // for positive scores int order == float order, and the tag gives the
    // FIRST max index on ties (matches jnp.argmax). pos <=> (best&~0x7F) > 0.
    // NOTE: no inline asm anywhere in this loop — ptxas owns scheduling.
#pragma unroll 8
    for (int l = 0; l < L_; ++l) {
        float4 lb = s_box[l];
        float  la = s_la[l];
        int tag = 127 - l;
#pragma unroll
        for (int q = 0; q < PPT; ++q) {
            float dx = fminf(lb.z, rx2[q]) - fmaxf(lb.x, rx[q]);
            float dy = fminf(lb.w, ry2[q]) - fmaxf(lb.y, ry[q]);
            float sy = fmaxf(dy, 0.0f);
            float sc = __fdividef(dx * sy, la + rA[q]);
            int pk = (int)((__float_as_uint(sc) & 0xFFFFFF80u) | (unsigned)tag);
            best[q] = max(best[q], pk);                      // signed IMNMX
        }
    }

    const int neg = __ldg(neg_flag);
    const float LOG01 = -2.3025850929940457f;   // log(0.1)
    const float LOG09 = -0.10536051565782628f;  // log(0.9)
    const float* cb = cls    + (size_t)b * 2 * P_;
    const float* db = deltas + (size_t)b * 4 * P_;

    float per_sum = 0.0f;

#pragma unroll
    for (int q = 0; q < PPT; ++q) {
        const int p  = pb + q * TPB;
        const int be = best[q];

        int  bidx = 127 - (be & 0x7F);
        bool pos  = ((be & (int)0xFFFFFF80) > 0) && (bidx > 0);

        float l0 = cb[p];
        float l1 = cb[P_ + p];
        float mx = fmaxf(l0, l1);
        float e0 = __expf(l0 - mx);
        float e1 = __expf(l1 - mx);
        float inv = __fdividef(1.0f, e0 + e1);
        float pr0 = e0 * inv, pr1 = e1 * inv;

        float per;
        if (pos) {
            float ce_pos = -(pr0 * LOG01 + pr1 * LOG09);
            float4 mb  = s_box[bidx];
            float2 mwh = s_wh[bidx];
            float rw = rx2[q] - rx[q];          // ~1 ulp vs exact rw; fine
            float rh = ry2[q] - ry[q];
            float invw = __fdividef(1.0f, rw);
            float invh = __fdividef(1.0f, rh);
            float tx = (mb.x - rx[q]) * invw;
            float ty = (mb.y - ry[q]) * invh;
            float tw = __logf(fmaxf(mwh.x * invw, 1e-8f));
            float th = __logf(fmaxf(mwh.y * invh, 1e-8f));
            float hx = huber1(tx - db[p]);
            float hy = huber1(ty - db[P_ + p]);
            float hw = huber1(tw - db[2 * P_ + p]);
            float hh = huber1(th - db[3 * P_ + p]);
            per = 0.5f * (hx + hy + hw + hh) + ce_pos;   // 2 * mean(huber)
        } else {
            float ce_neg = -(pr0 * LOG09 + pr1 * LOG01);
            per = (neg > 0) ? ce_neg : 0.0f;
        }
        per_sum += per;
    }

    // Deterministic block reduction
    s_red[tid] = per_sum;
    __syncthreads();
#pragma unroll
    for (int s = TPB / 2; s > 0; s >>= 1) {
        if (tid < s) s_red[tid] += s_red[tid + s];
        __syncthreads();
    }

    if (tid == 0) {
        g_partials[b * BLOCKS_PER_B + blockIdx.x] = s_red[0];
        __threadfence();
        unsigned t = atomicAdd(&g_count, 1u);
        s_last = (t == NB - 1);
    }
    __syncthreads();

    // Last block does the fixed-order final reduction (deterministic:
    // identical summation order regardless of which block is last).
    if (s_last) {
        double acc = 0.0;
#pragma unroll
        for (int i = tid; i < NB; i += TPB)
            acc += (double)__ldcg(&g_partials[i]);
        s_d[tid] = acc;
        __syncthreads();
#pragma unroll
        for (int st = TPB / 2; st > 0; st >>= 1) {
            if (tid < st) s_d[tid] += s_d[tid + st];
            __syncthreads();
        }
        if (tid == 0) {
            out[0]  = (float)s_d[0];
            g_count = 0;   // reset for next graph replay
        }
    }
}

extern "C" void kernel_launch(void* const* d_in, const int* in_sizes, int n_in,
                              void* d_out, int out_size)
{
    const float* cls    = (const float*)d_in[0];  // [B, 2P]
    const float* deltas = (const float*)d_in[1];  // [B, 4P]
    const float* roi    = (const float*)d_in[2];  // [B, P, 4]
    const float* labels = (const float*)d_in[3];  // [B, L, 4]
    const int*   negf   = (const int*)  d_in[4];  // scalar

    dim3 grid(BLOCKS_PER_B, B_);
    classifier_loss_kernel<<<grid, TPB>>>(cls, deltas, roi, labels, negf,
                                          (float*)d_out);
    (void)in_sizes; (void)n_in; (void)out_size;
}